// round 13
// baseline (speedup 1.0000x reference)
#include <cuda_runtime.h>
#include <cstdint>
#include <cstddef>

// ---------------------------------------------------------------------------
// NonOverlappingConv1d as GEMM, tf32 mma.sync.m16n8k8 (tcgen05 PTX rejected by
// this harness's ptxas target — verified R8).
//
//   out[b,o,p] = sum_kidx (W[o][kidx]/sqrt(128)) * x[b, kidx>>1, 2p+(kidx&1)]
//
// R13 = R12 + tail-wait fix: the 3-stage cp.async ring must deepen its
// wait_group as loads run out (wait<2>/wait<1>/wait<0>), otherwise the last
// two chunks are consumed before their copies land (R12's 3.3e-2 rel_err).
//
// Design: CTA tile 64(o) x 256(p), 112 KB smem -> 2 CTAs/SM for
// phase-independent latency/barrier hiding. A (64x256 weights) staged once in
// fragment order with 1/sqrt(128) folded; B (x) cp.async.cg 16B into
// row-major SMEM (2KB rows, odd rows XOR 64B), 16 K-chunks of 16 kidx,
// 3-stage ring. Fragments: A via LDS.128, B via 2 conflict-free LDS.32.
// 8 warps = 2(m) x 4(n); warp tile 32(o) x 64(p). o-pair CTAs adjacent in
// blockIdx.x so the duplicated x read hits L2.
// ---------------------------------------------------------------------------

namespace {
constexpr int kCin = 128, kDin = 8192, kP = 4096, kO = 128, kK = 256;
constexpr int TILE_P = 256;
constexpr int TILE_O = 64;
constexpr int THREADS = 256;
constexpr int NCH = 16;                    // K-chunks of 16 kidx (8 c-rows)
constexpr int STAGES = 3;
constexpr int ROWB = TILE_P * 2 * 4;       // 2048 B per B row (512 floats)
constexpr uint32_t A_BYTES = 65536u;       // 64 x 256 fp32
constexpr uint32_t B_STAGE = 8u * ROWB;    // 16384 B
constexpr uint32_t SMEM_BYTES = A_BYTES + STAGES * B_STAGE;   // 114688
}  // namespace

__device__ __forceinline__ uint32_t smem_u32(const void* p) {
  uint32_t a;
  asm("{ .reg .u64 t; cvta.to.shared.u64 t, %1; cvt.u32.u64 %0, t; }"
      : "=r"(a) : "l"(p));
  return a;
}
__device__ __forceinline__ float to_tf32(float x) {
  uint32_t u;
  asm("cvt.rna.tf32.f32 %0, %1;" : "=r"(u) : "f"(x));
  return __uint_as_float(u);
}
__device__ __forceinline__ uint32_t tf32u(float x) {
  uint32_t u;
  asm("cvt.rna.tf32.f32 %0, %1;" : "=r"(u) : "f"(x));
  return u;
}
__device__ __forceinline__ void cp16(uint32_t dst, const void* src) {
  asm volatile("cp.async.cg.shared.global [%0], [%1], 16;"
               :: "r"(dst), "l"(src) : "memory");
}
__device__ __forceinline__ void cp_commit() {
  asm volatile("cp.async.commit_group;" ::: "memory");
}
template <int N>
__device__ __forceinline__ void cp_wait() {
  asm volatile("cp.async.wait_group %0;" :: "n"(N) : "memory");
}
__device__ __forceinline__ float lds32(uint32_t a) {
  float f;
  asm volatile("ld.shared.f32 %0, [%1];" : "=f"(f) : "r"(a));
  return f;
}
__device__ __forceinline__ void mma_tf32(float d[4], const uint32_t a[4],
                                         const uint32_t b[2]) {
  asm volatile(
      "mma.sync.aligned.m16n8k8.row.col.f32.tf32.tf32.f32 "
      "{%0,%1,%2,%3}, {%4,%5,%6,%7}, {%8,%9}, {%0,%1,%2,%3};"
      : "+f"(d[0]), "+f"(d[1]), "+f"(d[2]), "+f"(d[3])
      : "r"(a[0]), "r"(a[1]), "r"(a[2]), "r"(a[3]), "r"(b[0]), "r"(b[1]));
}

__global__ __launch_bounds__(THREADS, 2)
void conv1d_tf32_2cta(const float* __restrict__ x,
                      const float* __restrict__ w,
                      float* __restrict__ out) {
  extern __shared__ char smem[];
  float* sA = reinterpret_cast<float*>(smem);
  const uint32_t sBu = smem_u32(smem) + A_BYTES;

  const int tid = threadIdx.x;
  const int lane = tid & 31;
  const int wid = tid >> 5;
  const int b = blockIdx.y;
  const int ohalf = blockIdx.x & 1;          // o-pair adjacent -> L2 sharing
  const int p0 = (blockIdx.x >> 1) * TILE_P;
  const int o_base = ohalf * TILE_O;

  // ------------------------------------------------------------------
  // Stage A (64x256 weight o-half) once, fragment order, scale folded.
  // Slot (ol,kidx): mt=ol>>4 (0..3), kt=kidx>>3, r=ol&15, c=kidx&7
  //   lane=(r&7)*4+(c&3), reg=(r>>3)+((c>>2)<<1)
  //   float offset = (mt*32+kt)*128 + lane*4 + reg
  // ------------------------------------------------------------------
  const float scale = 0.08838834764831845f;   // 1/sqrt(128)
  #pragma unroll
  for (int it = 0; it < 16; ++it) {
    int lin = it * THREADS + tid;
    int ol = lin >> 6;                        // 0..63
    int j = lin & 63;
    float4 w4 =
        *reinterpret_cast<const float4*>(w + (o_base + ol) * kK + 4 * j);
    float v[4] = {to_tf32(w4.x * scale), to_tf32(w4.y * scale),
                  to_tf32(w4.z * scale), to_tf32(w4.w * scale)};
    int mt = ol >> 4, r = ol & 15, kt = j >> 1;
    float* base = sA + (mt * 32 + kt) * 128;
    #pragma unroll
    for (int e = 0; e < 4; ++e) {
      int c = (4 * j + e) & 7;
      int ln = (r & 7) * 4 + (c & 3);
      int rg = (r >> 3) + ((c >> 2) << 1);
      base[ln * 4 + rg] = v[e];
    }
  }

  // ------------------------------------------------------------------
  // B chunk loader: chunk ch = c rows [8ch, 8ch+8), 512 floats per row.
  // thread -> (row_off = tid>>7 in {0,1}, col16 = tid&127); q: rows +2q.
  // Odd rows XOR 64B.
  // ------------------------------------------------------------------
  const int ld_row_off = tid >> 7;
  const int ld_c16 = tid & 127;
  auto load_chunk = [&](int ch, int slot) {
    const float* xb =
        x + ((size_t)(b * kCin + ch * 8 + ld_row_off)) * kDin + 2 * p0 +
        4 * ld_c16;
    uint32_t d0 = sBu + (uint32_t)slot * B_STAGE +
                  (uint32_t)ld_row_off * ROWB +
                  ((uint32_t)(ld_c16 * 16) ^ ((uint32_t)(ld_row_off & 1) << 6));
    #pragma unroll
    for (int q = 0; q < 4; ++q) {
      cp16(d0 + (uint32_t)(2 * q) * ROWB, xb + (size_t)(2 * q) * kDin);
    }
    cp_commit();
  };

  // ------------------------------------------------------------------
  // Warp tiling: 8 warps = 2(m) x 4(n); warp tile 32(o) x 64(p).
  // ------------------------------------------------------------------
  const int wm = (wid >> 2) * 32;            // 0 or 32
  const int wn = (wid & 3) * 64;             // 0..192
  const int gid = lane >> 2, tq = lane & 3;
  const int amt0 = (wm >> 4);                // 0 or 2

  float acc[2][8][4];
  #pragma unroll
  for (int i = 0; i < 2; ++i)
    #pragma unroll
    for (int j2 = 0; j2 < 8; ++j2)
      #pragma unroll
      for (int r2 = 0; r2 < 4; ++r2) acc[i][j2][r2] = 0.f;

  // B fragment (nt,k8l): reg0 row 4k8l+(tq>>1), reg1 row +2;
  // byte-in-row = 8*(wn+8nt+gid) + 4*(tq&1); XOR 64 iff row odd.
  const uint32_t bpar = ((uint32_t)(tq >> 1) & 1u) << 6;
  const uint32_t brow0 = (uint32_t)(tq >> 1) * ROWB;
  const uint32_t bq0 = (uint32_t)(8 * (wn + gid) + 4 * (tq & 1));

  auto compute_chunk = [&](int ch, int slot) {
    const uint32_t bb = sBu + (uint32_t)slot * B_STAGE + brow0;
    #pragma unroll
    for (int k8l = 0; k8l < 2; ++k8l) {
      const int kt = ch * 2 + k8l;
      uint32_t afr[2][4];
      #pragma unroll
      for (int mt2 = 0; mt2 < 2; ++mt2) {
        uint4 av = *reinterpret_cast<const uint4*>(
            sA + ((amt0 + mt2) * 32 + kt) * 128 + lane * 4);
        afr[mt2][0] = av.x; afr[mt2][1] = av.y;
        afr[mt2][2] = av.z; afr[mt2][3] = av.w;
      }
      const uint32_t rb = bb + (uint32_t)(4 * k8l) * ROWB;
      uint32_t bfr[8][2];
      #pragma unroll
      for (int nt = 0; nt < 8; ++nt) {
        uint32_t loc = (bq0 + (uint32_t)(64 * nt)) ^ bpar;
        bfr[nt][0] = tf32u(lds32(rb + loc));
        bfr[nt][1] = tf32u(lds32(rb + 2u * ROWB + loc));
      }
      #pragma unroll
      for (int mt2 = 0; mt2 < 2; ++mt2)
        #pragma unroll
        for (int nt = 0; nt < 8; ++nt)
          mma_tf32(acc[mt2][nt], afr[mt2], bfr[nt]);
    }
  };

  // ------------------------------------------------------------------
  // 3-stage cp.async ring over 16 chunks.
  // TAIL FIX: once no more loads are issued, the wait depth must shrink so
  // the chunk being consumed is actually guaranteed complete:
  //   ch < 14 -> wait<2>   (3 groups in flight)
  //   ch = 14 -> wait<1>   (2 groups in flight)
  //   ch = 15 -> wait<0>   (1 group in flight)
  // ------------------------------------------------------------------
  load_chunk(0, 0);
  load_chunk(1, 1);
  load_chunk(2, 2);

  int slot = 0;
  #pragma unroll 1
  for (int ch = 0; ch < NCH; ++ch) {
    if (ch < NCH - 2) {
      cp_wait<STAGES - 1>();
    } else if (ch == NCH - 2) {
      cp_wait<1>();
    } else {
      cp_wait<0>();
    }
    __syncthreads();                 // chunk ch visible CTA-wide (+A on ch=0)
    compute_chunk(ch, slot);
    __syncthreads();                 // all warps done reading slot
    if (ch + STAGES < NCH) load_chunk(ch + STAGES, slot);
    slot = (slot == STAGES - 1) ? 0 : slot + 1;
  }

  // ------------------------------------------------------------------
  // Epilogue (scale pre-folded): float2 stores.
  // D frag: c0:(g,2tq) c1:(g,2tq+1) c2:(g+8,2tq) c3:(g+8,2tq+1)
  // ------------------------------------------------------------------
  float* ob = out + (size_t)b * kO * kP;
  #pragma unroll
  for (int mt2 = 0; mt2 < 2; ++mt2) {
    int o0 = o_base + wm + mt2 * 16 + gid;
    #pragma unroll
    for (int nt = 0; nt < 8; ++nt) {
      int p = p0 + wn + nt * 8 + 2 * tq;
      *reinterpret_cast<float2*>(ob + (size_t)o0 * kP + p) =
          make_float2(acc[mt2][nt][0], acc[mt2][nt][1]);
      *reinterpret_cast<float2*>(ob + (size_t)(o0 + 8) * kP + p) =
          make_float2(acc[mt2][nt][2], acc[mt2][nt][3]);
    }
  }
}

extern "C" void kernel_launch(void* const* d_in, const int* in_sizes, int n_in,
                              void* d_out, int out_size) {
  const float* x = (const float*)d_in[0];
  const float* w = (const float*)d_in[1];
  if (n_in >= 2 && in_sizes[0] == kO * kK) {   // defensive operand id by size
    const float* t = x; x = w; w = t;
  }
  (void)out_size;

  cudaFuncSetAttribute(conv1d_tf32_2cta,
                       cudaFuncAttributeMaxDynamicSharedMemorySize, SMEM_BYTES);

  dim3 grid(2 * (kP / TILE_P), 32);   // (32, 32) = 1024 CTAs, o-pairs adjacent
  conv1d_tf32_2cta<<<grid, THREADS, SMEM_BYTES>>>(x, w, (float*)d_out);
}

// round 14
// speedup vs baseline: 1.0796x; 1.0796x over previous
#include <cuda_runtime.h>
#include <cstdint>
#include <cstddef>

// ---------------------------------------------------------------------------
// NonOverlappingConv1d as GEMM, tf32 mma.sync.m16n8k8 (tcgen05 PTX rejected by
// this harness's ptxas target — verified R8).
//
//   out[b,o,p] = sum_kidx (W[o][kidx]/sqrt(128)) * x[b, kidx>>1, 2p+(kidx&1)]
//
// R14 = R11 (best config: 512 thr / 16 warps, CTA 128x256, warp 64x32) plus:
//  1) B fragments passed to HMMA as RAW fp32 bits (HW ignores low mantissa
//     bits for tf32 operands — CUTLASS fast-path). Removes 16 CVTs per k8
//     per warp; instruction mix was the measured bottleneck (tensor pinned
//     at ~33% = its share of issue slots across all prior designs).
//     A is still RNA-rounded (and 1/sqrt(128)-folded) once at staging.
//  2) Single __syncthreads per chunk, 3-buffer cp.async ring:
//     wait -> sync -> load(ch+2) -> compute(ch). Halves barriers, 2-deep
//     prefetch. Smem = A 128K + 3x32K = 224 KB.
//
// A (weights): fragment-order SMEM, staged once/CTA, LDS.128 conflict-free.
// B (x): cp.async.cg 16B -> row-major SMEM (2KB rows, odd rows XOR 64B),
//        8 K-chunks of 32 kidx; fragments via 2 conflict-free LDS.32.
// ---------------------------------------------------------------------------

namespace {
constexpr int kCin = 128, kDin = 8192, kP = 4096, kO = 128, kK = 256;
constexpr int TILE_P = 256;
constexpr int THREADS = 512;
constexpr int NCH = 8;                     // K-chunks of 32 kidx (16 c-rows)
constexpr int ROWB = TILE_P * 2 * 4;       // 2048 B per B row (512 floats)
constexpr uint32_t A_BYTES = 131072u;      // 128 x 256 fp32
constexpr uint32_t B_STAGE = 16u * ROWB;   // 32768 B
constexpr uint32_t SMEM_BYTES = A_BYTES + 3u * B_STAGE;   // 229376
}  // namespace

__device__ __forceinline__ uint32_t smem_u32(const void* p) {
  uint32_t a;
  asm("{ .reg .u64 t; cvta.to.shared.u64 t, %1; cvt.u32.u64 %0, t; }"
      : "=r"(a) : "l"(p));
  return a;
}
__device__ __forceinline__ float to_tf32(float x) {
  uint32_t u;
  asm("cvt.rna.tf32.f32 %0, %1;" : "=r"(u) : "f"(x));
  return __uint_as_float(u);
}
__device__ __forceinline__ void cp16(uint32_t dst, const void* src) {
  asm volatile("cp.async.cg.shared.global [%0], [%1], 16;"
               :: "r"(dst), "l"(src) : "memory");
}
__device__ __forceinline__ void cp_commit() {
  asm volatile("cp.async.commit_group;" ::: "memory");
}
template <int N>
__device__ __forceinline__ void cp_wait() {
  asm volatile("cp.async.wait_group %0;" :: "n"(N) : "memory");
}
__device__ __forceinline__ uint32_t lds32u(uint32_t a) {
  uint32_t v;
  asm volatile("ld.shared.b32 %0, [%1];" : "=r"(v) : "r"(a));
  return v;
}
__device__ __forceinline__ void mma_tf32(float d[4], const uint32_t a[4],
                                         const uint32_t b[2]) {
  asm volatile(
      "mma.sync.aligned.m16n8k8.row.col.f32.tf32.tf32.f32 "
      "{%0,%1,%2,%3}, {%4,%5,%6,%7}, {%8,%9}, {%0,%1,%2,%3};"
      : "+f"(d[0]), "+f"(d[1]), "+f"(d[2]), "+f"(d[3])
      : "r"(a[0]), "r"(a[1]), "r"(a[2]), "r"(a[3]), "r"(b[0]), "r"(b[1]));
}

__global__ __launch_bounds__(THREADS, 1)
void conv1d_tf32_fast(const float* __restrict__ x,
                      const float* __restrict__ w,
                      float* __restrict__ out) {
  extern __shared__ char smem[];
  float* sA = reinterpret_cast<float*>(smem);
  const uint32_t sBu = smem_u32(smem) + A_BYTES;

  const int tid = threadIdx.x;
  const int lane = tid & 31;
  const int wid = tid >> 5;
  const int b = blockIdx.y;
  const int p0 = blockIdx.x * TILE_P;

  // ------------------------------------------------------------------
  // Stage A (128x256 weights) once, fragment order, RNA + scale folded.
  // Slot (o,kidx): mt=o>>4, kt=kidx>>3, r=o&15, c=kidx&7
  //   lane=(r&7)*4+(c&3), reg=(r>>3)+((c>>2)<<1)
  //   float offset = (mt*32+kt)*128 + lane*4 + reg
  // ------------------------------------------------------------------
  const float scale = 0.08838834764831845f;   // 1/sqrt(128)
  #pragma unroll
  for (int it = 0; it < 16; ++it) {
    int lin = it * THREADS + tid;
    int o = lin >> 6;
    int j = lin & 63;
    float4 w4 = *reinterpret_cast<const float4*>(w + o * kK + 4 * j);
    float v[4] = {to_tf32(w4.x * scale), to_tf32(w4.y * scale),
                  to_tf32(w4.z * scale), to_tf32(w4.w * scale)};
    int mt = o >> 4, r = o & 15, kt = j >> 1;
    float* base = sA + (mt * 32 + kt) * 128;
    #pragma unroll
    for (int e = 0; e < 4; ++e) {
      int c = (4 * j + e) & 7;
      int ln = (r & 7) * 4 + (c & 3);
      int rg = (r >> 3) + ((c >> 2) << 1);
      base[ln * 4 + rg] = v[e];
    }
  }

  // ------------------------------------------------------------------
  // B chunk loader: chunk ch = c rows [16ch,16ch+16), 512 floats each.
  // 512 threads: row = (tid>>7) + 4q, col16 = tid&127. Odd rows XOR 64B.
  // ------------------------------------------------------------------
  const int ld_row_off = tid >> 7;            // 0..3
  const int ld_c16 = tid & 127;
  auto load_chunk = [&](int ch, int slot) {
    const float* xb =
        x + ((size_t)(b * kCin + ch * 16 + ld_row_off)) * kDin + 2 * p0 +
        4 * ld_c16;
    uint32_t d0 = sBu + (uint32_t)slot * B_STAGE +
                  (uint32_t)ld_row_off * ROWB +
                  ((uint32_t)(ld_c16 * 16) ^ ((uint32_t)(ld_row_off & 1) << 6));
    #pragma unroll
    for (int q = 0; q < 4; ++q) {     // rows ld_row_off + 4q (parity fixed)
      cp16(d0 + (uint32_t)(4 * q) * ROWB, xb + (size_t)(4 * q) * kDin);
    }
    cp_commit();
  };

  // ------------------------------------------------------------------
  // Warp tiling: 16 warps = 2(m) x 8(n), warp tile 64 x 32.
  // ------------------------------------------------------------------
  const int wm = (wid >> 3) * 64;            // 0 or 64
  const int wn = (wid & 7) * 32;             // 0..224
  const int gid = lane >> 2, tq = lane & 3;
  const float* sAw = sA + (wm >> 4) * 32 * 128;

  float acc[4][4][4];
  #pragma unroll
  for (int i = 0; i < 4; ++i)
    #pragma unroll
    for (int j2 = 0; j2 < 4; ++j2)
      #pragma unroll
      for (int r2 = 0; r2 < 4; ++r2) acc[i][j2][r2] = 0.f;

  // B fragment (nt,k8): reg0 row 4k8+(tq>>1), reg1 row +2;
  // byte-in-row = 8*(wn+8nt+gid) + 4*(tq&1); XOR 64 iff row odd.
  const uint32_t bpar = ((uint32_t)(tq >> 1) & 1u) << 6;
  const uint32_t brow0 = (uint32_t)(tq >> 1) * ROWB;
  const uint32_t bq0 = (uint32_t)(8 * (wn + gid) + 4 * (tq & 1));

  auto compute_chunk = [&](int ch, int slot) {
    const uint32_t bb = sBu + (uint32_t)slot * B_STAGE + brow0;
    #pragma unroll
    for (int k8 = 0; k8 < 4; ++k8) {
      const int kt = ch * 4 + k8;
      uint32_t afr[4][4];
      #pragma unroll
      for (int mt2 = 0; mt2 < 4; ++mt2) {
        uint4 av = *reinterpret_cast<const uint4*>(
            sAw + (mt2 * 32 + kt) * 128 + lane * 4);
        afr[mt2][0] = av.x; afr[mt2][1] = av.y;
        afr[mt2][2] = av.z; afr[mt2][3] = av.w;
      }
      const uint32_t rb = bb + (uint32_t)(4 * k8) * ROWB;
      uint32_t bfr[4][2];
      #pragma unroll
      for (int nt = 0; nt < 4; ++nt) {
        uint32_t loc = (bq0 + (uint32_t)(64 * nt)) ^ bpar;
        // Raw fp32 bits: HMMA.tf32 ignores low mantissa bits (truncation).
        bfr[nt][0] = lds32u(rb + loc);
        bfr[nt][1] = lds32u(rb + 2u * ROWB + loc);
      }
      #pragma unroll
      for (int mt2 = 0; mt2 < 4; ++mt2)
        #pragma unroll
        for (int nt = 0; nt < 4; ++nt)
          mma_tf32(acc[mt2][nt], afr[mt2], bfr[nt]);
    }
  };

  // ------------------------------------------------------------------
  // 3-buffer cp.async ring, ONE barrier per chunk (CUTLASS ordering):
  //   preload chunks 0,1; iter ch: wait -> sync -> load(ch+2) -> compute(ch)
  // Write slot (ch+2)%3 == slot read at iter ch-1; the sync at top of iter
  // ch orders all reads of that slot before the new copies.
  // Wait depth: 2 groups in flight -> wait<1>; final iter -> wait<0>.
  // ------------------------------------------------------------------
  load_chunk(0, 0);
  load_chunk(1, 1);

  #pragma unroll 1
  for (int ch = 0; ch < NCH; ++ch) {
    if (ch < NCH - 1) cp_wait<1>(); else cp_wait<0>();
    __syncthreads();                 // chunk ch visible; prior slot reads done
    if (ch + 2 < NCH) load_chunk(ch + 2, (ch + 2) % 3);
    compute_chunk(ch, ch % 3);
  }

  // ------------------------------------------------------------------
  // Epilogue (scale pre-folded): float2 stores.
  // D frag: c0:(g,2tq) c1:(g,2tq+1) c2:(g+8,2tq) c3:(g+8,2tq+1)
  // ------------------------------------------------------------------
  float* ob = out + (size_t)b * kO * kP;
  #pragma unroll
  for (int mt2 = 0; mt2 < 4; ++mt2) {
    int o0 = wm + mt2 * 16 + gid;
    #pragma unroll
    for (int nt = 0; nt < 4; ++nt) {
      int p = p0 + wn + nt * 8 + 2 * tq;
      *reinterpret_cast<float2*>(ob + (size_t)o0 * kP + p) =
          make_float2(acc[mt2][nt][0], acc[mt2][nt][1]);
      *reinterpret_cast<float2*>(ob + (size_t)(o0 + 8) * kP + p) =
          make_float2(acc[mt2][nt][2], acc[mt2][nt][3]);
    }
  }
}

extern "C" void kernel_launch(void* const* d_in, const int* in_sizes, int n_in,
                              void* d_out, int out_size) {
  const float* x = (const float*)d_in[0];
  const float* w = (const float*)d_in[1];
  if (n_in >= 2 && in_sizes[0] == kO * kK) {   // defensive operand id by size
    const float* t = x; x = w; w = t;
  }
  (void)out_size;

  cudaFuncSetAttribute(conv1d_tf32_fast,
                       cudaFuncAttributeMaxDynamicSharedMemorySize, SMEM_BYTES);

  dim3 grid(kP / TILE_P, 32);   // (16, 32) = 512 CTAs
  conv1d_tf32_fast<<<grid, THREADS, SMEM_BYTES>>>(x, w, (float*)d_out);
}

// round 15
// speedup vs baseline: 1.5991x; 1.4813x over previous
#include <cuda_runtime.h>
#include <cuda_fp16.h>
#include <cstdint>
#include <cstddef>

// ---------------------------------------------------------------------------
// NonOverlappingConv1d as GEMM, fp16 mma.sync.m16n8k16 with fp32 accumulate.
// tf32 m16n8k8 designs all pinned at ~86us = HMMA instruction-count wall;
// fp16 k16 halves the HMMA count at identical 10-bit mantissa precision.
// (tcgen05 PTX rejected by this harness's ptxas target — verified R8.)
//
//   out[b,o,p] = sum_kidx (W[o][kidx]/sqrt(128)) * x[b, kidx>>1, 2p+(kidx&1)]
//
// A (weights): half, fragment-order SMEM (64 KB), staged once, scale folded.
// B (x): LDG float4 -> cvt.rn.f16x2 -> STS.128 into per-c-row half2 layout
//        (1 KB rows, XOR (row&3)<<5); the (2p,2p+1) interleave IS the half2.
//        4 K-chunks of 64 kidx, double-buffered, ldg/compute/sts overlap.
// Fragments: A = LDS.128 conflict-free; B = 2x LDS.32 conflict-free
//        (banks 8*(nt^tq)+gid, bijective over the warp).
// 16 warps = 2(m) x 8(n); warp tile 64 x 32; CTA 128(o) x 256(p); grid 512.
// ---------------------------------------------------------------------------

namespace {
constexpr int kCin = 128, kDin = 8192, kP = 4096, kO = 128, kK = 256;
constexpr int TILE_P = 256;
constexpr int THREADS = 512;
constexpr int NCH = 4;                      // K-chunks of 64 kidx (32 c-rows)
constexpr int ROW_BYTES = 1024;             // 256 half2 per c-row
constexpr uint32_t A_BYTES = 65536u;        // 128 x 256 half
constexpr uint32_t B_STAGE = 32u * ROW_BYTES;   // 32768 B
constexpr uint32_t SMEM_BYTES = A_BYTES + 2u * B_STAGE;   // 131072
}  // namespace

__device__ __forceinline__ uint32_t smem_u32(const void* p) {
  uint32_t a;
  asm("{ .reg .u64 t; cvta.to.shared.u64 t, %1; cvt.u32.u64 %0, t; }"
      : "=r"(a) : "l"(p));
  return a;
}
__device__ __forceinline__ uint32_t lds32u(uint32_t a) {
  uint32_t v;
  asm volatile("ld.shared.b32 %0, [%1];" : "=r"(v) : "r"(a));
  return v;
}
__device__ __forceinline__ uint32_t pack_h2(float lo, float hi) {
  uint32_t r;
  asm("cvt.rn.f16x2.f32 %0, %1, %2;" : "=r"(r) : "f"(hi), "f"(lo));
  return r;   // lo in bits [0:16), hi in [16:32)
}
__device__ __forceinline__ void sts128(uint32_t a, uint32_t r0, uint32_t r1,
                                       uint32_t r2, uint32_t r3) {
  asm volatile("st.shared.v4.b32 [%0], {%1,%2,%3,%4};"
               :: "r"(a), "r"(r0), "r"(r1), "r"(r2), "r"(r3) : "memory");
}
__device__ __forceinline__ void mma_f16(float d[4], const uint32_t a[4],
                                        const uint32_t b[2]) {
  asm volatile(
      "mma.sync.aligned.m16n8k16.row.col.f32.f16.f16.f32 "
      "{%0,%1,%2,%3}, {%4,%5,%6,%7}, {%8,%9}, {%0,%1,%2,%3};"
      : "+f"(d[0]), "+f"(d[1]), "+f"(d[2]), "+f"(d[3])
      : "r"(a[0]), "r"(a[1]), "r"(a[2]), "r"(a[3]), "r"(b[0]), "r"(b[1]));
}

__global__ __launch_bounds__(THREADS, 1)
void conv1d_fp16_k16(const float* __restrict__ x,
                     const float* __restrict__ w,
                     float* __restrict__ out) {
  extern __shared__ char smem[];
  __half* sAh = reinterpret_cast<__half*>(smem);
  const uint32_t sBu = smem_u32(smem) + A_BYTES;

  const int tid = threadIdx.x;
  const int lane = tid & 31;
  const int wid = tid >> 5;
  const int b = blockIdx.y;
  const int p0 = blockIdx.x * TILE_P;

  // ---- B staging: row = tid>>4 (32 rows), seg = tid&15.
  // Quarter s: STS.128 at (row*1024 + s*256 + seg*16) ^ ((row&3)<<5),
  // sourcing floats [128s + 8seg, +8) of row c = 32ch + row.
  const int brow = tid >> 4;
  const int bseg = tid & 15;
  float4 stg[8];

  auto ldg_chunk = [&](int ch) {
    const float* xb =
        x + ((size_t)(b * kCin + ch * 32 + brow)) * kDin + 2 * p0 + 8 * bseg;
    #pragma unroll
    for (int s = 0; s < 4; ++s) {
      stg[2 * s]     = *reinterpret_cast<const float4*>(xb + 128 * s);
      stg[2 * s + 1] = *reinterpret_cast<const float4*>(xb + 128 * s + 4);
    }
  };

  auto sts_chunk = [&](int buf) {
    uint32_t base = (sBu + (uint32_t)buf * B_STAGE + (uint32_t)brow * 1024u +
                     (uint32_t)(bseg * 16)) ^ ((uint32_t)(brow & 3) << 5);
    #pragma unroll
    for (int s = 0; s < 4; ++s) {
      sts128(base + (uint32_t)(256 * s),
             pack_h2(stg[2 * s].x, stg[2 * s].y),
             pack_h2(stg[2 * s].z, stg[2 * s].w),
             pack_h2(stg[2 * s + 1].x, stg[2 * s + 1].y),
             pack_h2(stg[2 * s + 1].z, stg[2 * s + 1].w));
    }
  };

  ldg_chunk(0);   // issue early, latency covered by A staging

  // ---- Stage A -> half, fragment order, 1/sqrt(128) folded.
  // Block (mt=o>>4, kt=kidx>>4); r=o&15, c=kidx&15;
  // lane=(r&7)*4+((c&7)>>1); halfpos=4*(c>>3)+2*(r>>3)+(c&1);
  // half index = (mt*16+kt)*256 + lane*8 + halfpos.
  const float scale = 0.08838834764831845f;
  #pragma unroll
  for (int it = 0; it < 16; ++it) {
    int lin = it * THREADS + tid;
    int o = lin >> 6;
    int j = lin & 63;
    float4 w4 = *reinterpret_cast<const float4*>(w + o * kK + 4 * j);
    float v[4] = {w4.x * scale, w4.y * scale, w4.z * scale, w4.w * scale};
    int mt = o >> 4, r = o & 15;
    #pragma unroll
    for (int e = 0; e < 4; ++e) {
      int kidx = 4 * j + e;
      int kt = kidx >> 4, c = kidx & 15;
      int ln = (r & 7) * 4 + ((c & 7) >> 1);
      int hp = 4 * (c >> 3) + 2 * (r >> 3) + (c & 1);
      sAh[(mt * 16 + kt) * 256 + ln * 8 + hp] = __float2half_rn(v[e]);
    }
  }

  sts_chunk(0);
  __syncthreads();
  ldg_chunk(1);

  // ---- Warp tiling: 16 warps = 2(m) x 8(n); warp tile 64 x 32.
  const int wm = (wid >> 3) * 64;
  const int wn = (wid & 7) * 32;
  const int gid = lane >> 2, tq = lane & 3;
  const __half* sAw = sAh + (wm >> 4) * 16 * 256;

  float acc[4][4][4];
  #pragma unroll
  for (int i = 0; i < 4; ++i)
    #pragma unroll
    for (int j2 = 0; j2 < 4; ++j2)
      #pragma unroll
      for (int r2 = 0; r2 < 4; ++r2) acc[i][j2][r2] = 0.f;

  // B frag (kstep j, nt): reg0 row 8j+tq, reg1 row 8j+tq+4 (+4096 B);
  // loc = (4*(wn + 8nt + gid)) ^ (tq<<5)  [XOR after the nt add].
  const uint32_t brow0 = (uint32_t)tq * 1024u;
  const uint32_t bq0 = (uint32_t)(4 * (wn + gid));
  const uint32_t bxor = (uint32_t)tq << 5;

  auto compute_chunk = [&](int ch, int buf) {
    const uint32_t bb = sBu + (uint32_t)buf * B_STAGE + brow0;
    #pragma unroll
    for (int j = 0; j < 4; ++j) {
      const int kt = ch * 4 + j;
      uint32_t afr[4][4];
      #pragma unroll
      for (int mt2 = 0; mt2 < 4; ++mt2) {
        uint4 av = *reinterpret_cast<const uint4*>(
            sAw + (mt2 * 16 + kt) * 256 + lane * 8);
        afr[mt2][0] = av.x; afr[mt2][1] = av.y;
        afr[mt2][2] = av.z; afr[mt2][3] = av.w;
      }
      const uint32_t rb = bb + (uint32_t)(8 * j) * 1024u;
      uint32_t bfr[4][2];
      #pragma unroll
      for (int nt = 0; nt < 4; ++nt) {
        uint32_t loc = (bq0 + (uint32_t)(32 * nt)) ^ bxor;
        bfr[nt][0] = lds32u(rb + loc);
        bfr[nt][1] = lds32u(rb + 4096u + loc);
      }
      #pragma unroll
      for (int mt2 = 0; mt2 < 4; ++mt2)
        #pragma unroll
        for (int nt = 0; nt < 4; ++nt)
          mma_f16(acc[mt2][nt], afr[mt2], bfr[nt]);
    }
  };

  // ---- Mainloop: 4 chunks, double-buffered.
  #pragma unroll 1
  for (int ch = 0; ch < NCH; ++ch) {
    compute_chunk(ch, ch & 1);
    if (ch + 1 < NCH) {
      sts_chunk((ch + 1) & 1);
      __syncthreads();
      if (ch + 2 < NCH) ldg_chunk(ch + 2);
    }
  }

  // ---- Epilogue (scale folded): float2 stores.
  float* ob = out + (size_t)b * kO * kP;
  #pragma unroll
  for (int mt2 = 0; mt2 < 4; ++mt2) {
    int o0 = wm + mt2 * 16 + gid;
    #pragma unroll
    for (int nt = 0; nt < 4; ++nt) {
      int p = p0 + wn + nt * 8 + 2 * tq;
      *reinterpret_cast<float2*>(ob + (size_t)o0 * kP + p) =
          make_float2(acc[mt2][nt][0], acc[mt2][nt][1]);
      *reinterpret_cast<float2*>(ob + (size_t)(o0 + 8) * kP + p) =
          make_float2(acc[mt2][nt][2], acc[mt2][nt][3]);
    }
  }
}

extern "C" void kernel_launch(void* const* d_in, const int* in_sizes, int n_in,
                              void* d_out, int out_size) {
  const float* x = (const float*)d_in[0];
  const float* w = (const float*)d_in[1];
  if (n_in >= 2 && in_sizes[0] == kO * kK) {   // defensive operand id by size
    const float* t = x; x = w; w = t;
  }
  (void)out_size;

  cudaFuncSetAttribute(conv1d_fp16_k16,
                       cudaFuncAttributeMaxDynamicSharedMemorySize, SMEM_BYTES);

  dim3 grid(kP / TILE_P, 32);   // (16, 32) = 512 CTAs
  conv1d_fp16_k16<<<grid, THREADS, SMEM_BYTES>>>(x, w, (float*)d_out);
}